// round 14
// baseline (speedup 1.0000x reference)
#include <cuda_runtime.h>
#include <stdint.h>

#define NC    32
#define KC    16
#define DSUB  128
#define INF   4096
#define OF    2048
#define MAXTOK 2048

typedef unsigned long long ull;

__device__ float         g_lut[NC * KC * OF];
__device__ unsigned char g_idx[MAXTOK * NC];

// ---- packed f32x2 helpers --------------------------------------------------
__device__ __forceinline__ ull pk2(float x, float y) {
    ull r; asm("mov.b64 %0, {%1,%2};" : "=l"(r) : "f"(x), "f"(y)); return r;
}
__device__ __forceinline__ void upk2(ull v, float& x, float& y) {
    asm("mov.b64 {%0,%1}, %2;" : "=f"(x), "=f"(y) : "l"(v));
}
__device__ __forceinline__ ull fma2(ull a, ull b, ull c) {
    ull d; asm("fma.rn.f32x2 %0, %1, %2, %3;" : "=l"(d) : "l"(a), "l"(b), "l"(c)); return d;
}
__device__ __forceinline__ void lds_v2u64(ull& a, ull& b, const float* p) {
    asm("{ .reg .u64 t; cvta.to.shared.u64 t, %2; ld.shared.v2.u64 {%0,%1}, [t]; }"
        : "=l"(a), "=l"(b) : "l"(p));
}

#define IDX_CST   (DSUB * KC)                // 2048 floats

#define ACC16(A, xv) do {                                              \
    A[0]  = fmaf(xv, c0.x, A[0]);   A[1]  = fmaf(xv, c0.y, A[1]);      \
    A[2]  = fmaf(xv, c0.z, A[2]);   A[3]  = fmaf(xv, c0.w, A[3]);      \
    A[4]  = fmaf(xv, c1.x, A[4]);   A[5]  = fmaf(xv, c1.y, A[5]);      \
    A[6]  = fmaf(xv, c1.z, A[6]);   A[7]  = fmaf(xv, c1.w, A[7]);      \
    A[8]  = fmaf(xv, c2v.x, A[8]);  A[9]  = fmaf(xv, c2v.y, A[9]);     \
    A[10] = fmaf(xv, c2v.z, A[10]); A[11] = fmaf(xv, c2v.w, A[11]);    \
    A[12] = fmaf(xv, c3.x, A[12]);  A[13] = fmaf(xv, c3.y, A[13]);     \
    A[14] = fmaf(xv, c3.z, A[14]);  A[15] = fmaf(xv, c3.w, A[15]);     \
} while (0)

// ---------------------------------------------------------------------------
// Fused kernel v3, 512 threads.
// idx half REDESIGNED: x lives in registers (8 float4 per thread, loaded from
// GMEM before cst staging so DRAM latency overlaps it), quarter reduction via
// shfl_xor — no x tile, no red array: smem 102 KB -> 8.7 KB, and the main
// loop's only smem traffic is the broadcast cst loads.
// lut half: EXACT R11 512-thread version.
// ---------------------------------------------------------------------------
__global__ __launch_bounds__(512, 2) void fused_idx_lut(const float* __restrict__ x,
                                                        const float* __restrict__ cent,
                                                        const float* __restrict__ weight)
{
    extern __shared__ float sm[];
    const int id = blockIdx.x;
    const int w  = id >> 1;

    if ((id & 1) == 0) {
        // ================= idx half (v7: register-resident x) =================
        float* cst = sm;                 // [DSUB][KC]  2048 fl
        float* c2p = sm + IDX_CST;       // [16][8]
        float* c2s = c2p + 128;          // [16]

        const int c   = w & 31;
        const int tb  = (w >> 5) * 128;
        const int tid = threadIdx.x;

        const int lane  = tid & 31;
        const int wid   = tid >> 5;          // 0..15
        const int token = wid * 8 + (lane & 7);   // 0..127
        const int q     = lane >> 3;         // d-quarter 0..3
        const int dbase = q * 32;

        // x quarter -> registers FIRST (in flight during cst staging + c2)
        const float* xg = &x[(size_t)(tb + token) * INF + c * DSUB + dbase];
        float4 xv[8];
#pragma unroll
        for (int j = 0; j < 8; j++) xv[j] = *(const float4*)&xg[j * 4];

        for (int i = tid; i < KC * DSUB; i += 512) {
            int k = i >> 7, d = i & 127;
            cst[d * KC + k] = cent[(c * KC + k) * DSUB + d];
        }
        __syncthreads();

        if (tid < 128) {
            int k = tid >> 3, part = tid & 7;
            float s = 0.f;
            for (int d = part * 16; d < part * 16 + 16; d++) {
                float cv = cst[d * KC + k];
                s = fmaf(cv, cv, s);
            }
            c2p[k * 8 + part] = s;
        }
        __syncthreads();
        if (tid < 16) {
            float s = 0.f;
            for (int p = 0; p < 8; p++) s += c2p[tid * 8 + p];
            c2s[tid] = s;
        }
        __syncthreads();

        float acc[KC];
#pragma unroll
        for (int k = 0; k < KC; k++) acc[k] = 0.f;

#pragma unroll
        for (int j = 0; j < 8; j++) {
            float xa[4] = {xv[j].x, xv[j].y, xv[j].z, xv[j].w};
#pragma unroll
            for (int e = 0; e < 4; e++) {
                const int d = dbase + j * 4 + e;
                const float4* cp = (const float4*)&cst[d * KC];
                float4 c0 = cp[0], c1 = cp[1], c2v = cp[2], c3 = cp[3];
                float xval = xa[e];
                ACC16(acc, xval);
            }
        }

        // reduce quarters across lanes (xor 8: q0+q1 / q2+q3; xor 16: combine)
#pragma unroll
        for (int k = 0; k < KC; k++) {
            acc[k] += __shfl_xor_sync(0xFFFFFFFFu, acc[k], 8);
            acc[k] += __shfl_xor_sync(0xFFFFFFFFu, acc[k], 16);
        }

        if (q == 0) {   // lanes 0..7: one token each
            float best = 1e30f, second = 1e30f;
            int bi = 0, si = 0;
#pragma unroll
            for (int k = 0; k < KC; k++) {
                float v = c2s[k] - 2.f * acc[k];
                if (v < best)        { second = best; si = bi; best = v; bi = k; }
                else if (v < second) { second = v; si = k; }
            }
            if (second - best < 1e-3f) {
                const float* xrow = &x[(size_t)(tb + token) * INF + c * DSUB];
                double vb = 0.0, vs = 0.0;
                for (int d = 0; d < DSUB; d++) {
                    double xd = (double)xrow[d];
                    double cb = (double)cst[d * KC + bi];
                    double cs = (double)cst[d * KC + si];
                    vb += cb * (cb - 2.0 * xd);
                    vs += cs * (cs - 2.0 * xd);
                }
                if (vs < vb || (vs == vb && si < bi)) bi = si;
            }
            g_idx[(size_t)(tb + token) * NC + c] = (unsigned char)bi;
        }
    } else {
        // ================= lut half (R11 512-thread, verbatim) =================
        float* cst = sm;                     // [DSUB][KC]
        float* red = sm + IDX_CST;           // [3][KC][128]

        const int c   = w & 31;
        const int tid = threadIdx.x;
        const int dq  = tid >> 7;
        const int col = tid & 127;

        for (int i = tid; i < KC * DSUB; i += 512) {
            int k = i >> 7, d = i & 127;
            cst[d * KC + k] = cent[(c * KC + k) * DSUB + d];
        }
        __syncthreads();

        const int o = (w >> 5) * 128 + col;
        const float* wp = weight + (size_t)c * DSUB * OF + o + (size_t)(dq * 32) * OF;

        ull acc[8];
#pragma unroll
        for (int p = 0; p < 8; p++) acc[p] = 0ull;

#pragma unroll
        for (int half = 0; half < 2; half++) {
            float wv_[16];
#pragma unroll
            for (int i = 0; i < 16; i++) wv_[i] = wp[(size_t)(half * 16 + i) * OF];
#pragma unroll
            for (int i = 0; i < 16; i++) {
                ull wv = pk2(wv_[i], wv_[i]);
                const float* cp = &cst[(dq * 32 + half * 16 + i) * KC];
                ull a0, a1, a2, a3;
                lds_v2u64(a0, a1, cp);
                lds_v2u64(a2, a3, cp + 8);
                acc[0] = fma2(a0, wv, acc[0]);
                acc[1] = fma2(a1, wv, acc[1]);
                acc[2] = fma2(a2, wv, acc[2]);
                acc[3] = fma2(a3, wv, acc[3]);
                lds_v2u64(a0, a1, cp + 4);
                acc[4] = fma2(a0, wv, acc[4]);
                acc[5] = fma2(a1, wv, acc[5]);
                lds_v2u64(a2, a3, cp + 12);
                acc[6] = fma2(a2, wv, acc[6]);
                acc[7] = fma2(a3, wv, acc[7]);
            }
        }

        const int kmap[8] = {0, 1, 4, 5, 2, 3, 6, 7};

        if (dq != 0) {
#pragma unroll
            for (int p = 0; p < 8; p++) {
                float v0, v1; upk2(acc[p], v0, v1);
                int kp = kmap[p];
                red[(((dq - 1) * KC) + kp * 2 + 0) * 128 + col] = v0;
                red[(((dq - 1) * KC) + kp * 2 + 1) * 128 + col] = v1;
            }
        }
        __syncthreads();
        if (dq == 0) {
#pragma unroll
            for (int p = 0; p < 8; p++) {
                float v0, v1; upk2(acc[p], v0, v1);
                int k0 = kmap[p] * 2, k1 = k0 + 1;
                v0 = v0 + red[(0 * KC + k0) * 128 + col]
                        + red[(1 * KC + k0) * 128 + col]
                        + red[(2 * KC + k0) * 128 + col];
                v1 = v1 + red[(0 * KC + k1) * 128 + col]
                        + red[(1 * KC + k1) * 128 + col]
                        + red[(2 * KC + k1) * 128 + col];
                g_lut[(size_t)(c * KC + k0) * OF + o] = v0;
                g_lut[(size_t)(c * KC + k1) * OF + o] = v1;
            }
        }
    }
}

// ---------------------------------------------------------------------------
// K3: gather — EXACT Round-13 version (unchanged).
// ---------------------------------------------------------------------------
__global__ __launch_bounds__(512, 2) void gather_kernel(float* __restrict__ out,
                                                        const float* __restrict__ bias)
{
    extern __shared__ float sm[];
    float*         lut_s = sm;                                  // [512][32] floats
    unsigned char* idx_s = (unsigned char*)(sm + NC * KC * 32); // 512*32 B

    const int ob  = blockIdx.x * 32;
    const int tb  = blockIdx.y * 512;
    const int tid = threadIdx.x;

    for (int i = tid; i < NC * KC * 32 / 4; i += 512) {
        int row = i >> 3;
        int col = (i & 7) * 4;
        float4 v = *(const float4*)&g_lut[(size_t)row * OF + ob + col];
        *(float4*)&lut_s[row * 32 + col] = v;
    }
    {
        const uint4* src = (const uint4*)&g_idx[(size_t)tb * NC];
        uint4* dst = (uint4*)idx_s;
        for (int i = tid; i < (512 * NC) / 16; i += 512) dst[i] = src[i];
    }
    __syncthreads();

    const int oq = tid & 7;
    const int tg = tid >> 3;
    const float4 bv = *(const float4*)&bias[ob + oq * 4];
    const float* lut_q = lut_s + oq * 4;

    for (int t = tg; t < 512; t += 64) {
        uint4 a = *(const uint4*)&idx_s[t * NC];
        uint4 b = *(const uint4*)&idx_s[t * NC + 16];
        unsigned int iw[8] = {a.x, a.y, a.z, a.w, b.x, b.y, b.z, b.w};
        float x0 = 0.f, y0 = 0.f, z0 = 0.f, w0 = 0.f;
        float x1 = 0.f, y1 = 0.f, z1 = 0.f, w1 = 0.f;
#pragma unroll
        for (int c = 0; c < NC; c++) {
            unsigned int k = (iw[c >> 2] >> ((c & 3) * 8)) & 0xFFu;
            float4 v = *(const float4*)&lut_q[c * 512 + k * 32];
            if (c & 1) { x1 += v.x; y1 += v.y; z1 += v.z; w1 += v.w; }
            else       { x0 += v.x; y0 += v.y; z0 += v.z; w0 += v.w; }
        }
        float4 r;
        r.x = (x0 + x1) + bv.x;
        r.y = (y0 + y1) + bv.y;
        r.z = (z0 + z1) + bv.z;
        r.w = (w0 + w1) + bv.w;
        *(float4*)&out[(size_t)(tb + t) * OF + ob + oq * 4] = r;
    }
}

// ---------------------------------------------------------------------------
extern "C" void kernel_launch(void* const* d_in, const int* in_sizes, int n_in,
                              void* d_out, int out_size)
{
    const float* x      = (const float*)d_in[0];
    const float* cent   = (const float*)d_in[1];
    const float* weight = (const float*)d_in[2];
    const float* bias   = (const float*)d_in[4];
    float* out = (float*)d_out;

    const int ntok = in_sizes[0] / INF;

    const int FUSED_SMEM = (IDX_CST + 3 * KC * 128) * (int)sizeof(float);  // 32 KB
    const int G_SMEM     = NC * KC * 32 * (int)sizeof(float) + 512 * NC;   // 80 KB

    cudaFuncSetAttribute(fused_idx_lut, cudaFuncAttributeMaxDynamicSharedMemorySize, FUSED_SMEM);
    cudaFuncSetAttribute(gather_kernel, cudaFuncAttributeMaxDynamicSharedMemorySize, G_SMEM);

    const int nblk = (ntok / 128) * NC;      // 512
    fused_idx_lut<<<nblk * 2, 512, FUSED_SMEM>>>(x, cent, weight);
    gather_kernel<<<dim3(OF / 32, ntok / 512), 512, G_SMEM>>>(out, bias);
}

// round 15
// speedup vs baseline: 1.1615x; 1.1615x over previous
#include <cuda_runtime.h>
#include <stdint.h>

#define NC    32
#define KC    16
#define DSUB  128
#define INF   4096
#define OF    2048
#define MAXTOK 2048

typedef unsigned long long ull;

__device__ float         g_lut[NC * KC * OF];
__device__ unsigned char g_idx[MAXTOK * NC];

// ---- packed f32x2 helpers --------------------------------------------------
__device__ __forceinline__ ull pk2(float x, float y) {
    ull r; asm("mov.b64 %0, {%1,%2};" : "=l"(r) : "f"(x), "f"(y)); return r;
}
__device__ __forceinline__ void upk2(ull v, float& x, float& y) {
    asm("mov.b64 {%0,%1}, %2;" : "=f"(x), "=f"(y) : "l"(v));
}
__device__ __forceinline__ ull fma2(ull a, ull b, ull c) {
    ull d; asm("fma.rn.f32x2 %0, %1, %2, %3;" : "=l"(d) : "l"(a), "l"(b), "l"(c)); return d;
}
__device__ __forceinline__ void lds_v2u64(ull& a, ull& b, const float* p) {
    asm("{ .reg .u64 t; cvta.to.shared.u64 t, %2; ld.shared.v2.u64 {%0,%1}, [t]; }"
        : "=l"(a), "=l"(b) : "l"(p));
}

// smem layout for the idx half (floats)
#define XS_STRIDE 132
#define IDX_XS    (128 * XS_STRIDE)          // 16896
#define IDX_CST   (DSUB * KC)                // 2048
#define IDX_RED   (3 * 128 * 17)             // 6528
#define IDX_C2P   128
#define IDX_C2S   16
#define IDX_FLOATS (IDX_XS + IDX_CST + IDX_RED + IDX_C2P + IDX_C2S)

#define ACC16(A, xv) do {                                              \
    A[0]  = fmaf(xv, c0.x, A[0]);   A[1]  = fmaf(xv, c0.y, A[1]);      \
    A[2]  = fmaf(xv, c0.z, A[2]);   A[3]  = fmaf(xv, c0.w, A[3]);      \
    A[4]  = fmaf(xv, c1.x, A[4]);   A[5]  = fmaf(xv, c1.y, A[5]);      \
    A[6]  = fmaf(xv, c1.z, A[6]);   A[7]  = fmaf(xv, c1.w, A[7]);      \
    A[8]  = fmaf(xv, c2v.x, A[8]);  A[9]  = fmaf(xv, c2v.y, A[9]);     \
    A[10] = fmaf(xv, c2v.z, A[10]); A[11] = fmaf(xv, c2v.w, A[11]);    \
    A[12] = fmaf(xv, c3.x, A[12]);  A[13] = fmaf(xv, c3.y, A[13]);     \
    A[14] = fmaf(xv, c3.z, A[14]);  A[15] = fmaf(xv, c3.w, A[15]);     \
} while (0)

// ---------------------------------------------------------------------------
// Fused kernel — EXACT Round-13 version (the 76.3us best config).
// ---------------------------------------------------------------------------
__global__ __launch_bounds__(256, 2) void fused_idx_lut(const float* __restrict__ x,
                                                        const float* __restrict__ cent,
                                                        const float* __restrict__ weight)
{
    extern __shared__ float sm[];
    const int id = blockIdx.x;
    const int w  = id >> 1;

    if ((id & 1) == 0) {
        // ================= idx half =================
        float* xs  = sm;
        float* cst = sm + IDX_XS;
        float* red = cst + IDX_CST;
        float* c2p = red + IDX_RED;
        float* c2s = c2p + IDX_C2P;

        const int c   = w & 31;
        const int tb  = (w >> 5) * 128;
        const int tid = threadIdx.x;

#pragma unroll
        for (int b = 0; b < 2; b++) {
            float4 buf[8];
#pragma unroll
            for (int j = 0; j < 8; j++) {
                int i   = tid + (b * 8 + j) * 256;
                int row = i >> 5;
                int col = (i & 31) * 4;
                buf[j] = *(const float4*)&x[(size_t)(tb + row) * INF + c * DSUB + col];
            }
#pragma unroll
            for (int j = 0; j < 8; j++) {
                int i   = tid + (b * 8 + j) * 256;
                int row = i >> 5;
                int col = (i & 31) * 4;
                *(float4*)&xs[row * XS_STRIDE + col] = buf[j];
            }
        }
        for (int i = tid; i < KC * DSUB; i += 256) {
            int k = i >> 7, d = i & 127;
            cst[d * KC + k] = cent[(c * KC + k) * DSUB + d];
        }
        __syncthreads();

        if (tid < 128) {
            int k = tid >> 3, part = tid & 7;
            float s = 0.f;
            for (int d = part * 16; d < part * 16 + 16; d++) {
                float cv = cst[d * KC + k];
                s = fmaf(cv, cv, s);
            }
            c2p[k * 8 + part] = s;
        }
        __syncthreads();
        if (tid < 16) {
            float s = 0.f;
            for (int p = 0; p < 8; p++) s += c2p[tid * 8 + p];
            c2s[tid] = s;
        }
        __syncthreads();

        const int tp    = tid & 63;
        const int q     = tid >> 6;
        const int t0    = tp;
        const int t1    = tp + 64;
        const int dbase = q * 32;

        float acc0[KC], acc1[KC];
#pragma unroll
        for (int k = 0; k < KC; k++) { acc0[k] = 0.f; acc1[k] = 0.f; }

        const float* xrA = &xs[t0 * XS_STRIDE];
        const float* xrB = &xs[t1 * XS_STRIDE];
        for (int d0 = dbase; d0 < dbase + 32; d0 += 4) {
            float4 xqA = *(const float4*)&xrA[d0];
            float4 xqB = *(const float4*)&xrB[d0];
            float xa[4] = {xqA.x, xqA.y, xqA.z, xqA.w};
            float xb[4] = {xqB.x, xqB.y, xqB.z, xqB.w};
#pragma unroll
            for (int j = 0; j < 4; j++) {
                const float4* cp = (const float4*)&cst[(d0 + j) * KC];
                float4 c0 = cp[0], c1 = cp[1], c2v = cp[2], c3 = cp[3];
                float xvA = xa[j], xvB = xb[j];
                ACC16(acc0, xvA);
                ACC16(acc1, xvB);
            }
        }

        if (q != 0) {
#pragma unroll
            for (int k = 0; k < KC; k++) {
                red[((q - 1) * 128 + t0) * 17 + k] = acc0[k];
                red[((q - 1) * 128 + t1) * 17 + k] = acc1[k];
            }
        }
        __syncthreads();
        if (q == 0) {
#pragma unroll
            for (int pass = 0; pass < 2; pass++) {
                const int token   = pass ? t1 : t0;
                const float* accp = pass ? acc1 : acc0;
                const float* xr   = pass ? xrB : xrA;
                float best = 1e30f, second = 1e30f;
                int bi = 0, si = 0;
#pragma unroll
                for (int k = 0; k < KC; k++) {
                    float dot = accp[k]
                              + red[(0 * 128 + token) * 17 + k]
                              + red[(1 * 128 + token) * 17 + k]
                              + red[(2 * 128 + token) * 17 + k];
                    float v = c2s[k] - 2.f * dot;
                    if (v < best)        { second = best; si = bi; best = v; bi = k; }
                    else if (v < second) { second = v; si = k; }
                }
                if (second - best < 1e-3f) {
                    double vb = 0.0, vs = 0.0;
                    for (int d = 0; d < DSUB; d++) {
                        double xv = (double)xr[d];
                        double cb = (double)cst[d * KC + bi];
                        double cs = (double)cst[d * KC + si];
                        vb += cb * (cb - 2.0 * xv);
                        vs += cs * (cs - 2.0 * xv);
                    }
                    if (vs < vb || (vs == vb && si < bi)) bi = si;
                }
                g_idx[(size_t)(tb + token) * NC + c] = (unsigned char)bi;
            }
        }
    } else {
        // ================= lut half =================
        float* cst = sm;
        float* red = sm + IDX_CST;

        const int c   = w & 31;
        const int tid = threadIdx.x;
        const int dq  = tid >> 6;
        const int col = tid & 63;

        for (int i = tid; i < KC * DSUB; i += 256) {
            int k = i >> 7, d = i & 127;
            cst[d * KC + k] = cent[(c * KC + k) * DSUB + d];
        }
        __syncthreads();

        const int ob = (w >> 5) * 128;
        const int oA = ob + col;
        const int oB = ob + col + 64;
        const float* wp = weight + (size_t)c * DSUB * OF + (size_t)(dq * 32) * OF;

        ull accA[8], accB[8];
#pragma unroll
        for (int p = 0; p < 8; p++) { accA[p] = 0ull; accB[p] = 0ull; }

#pragma unroll
        for (int half = 0; half < 2; half++) {
            float wA[16], wB[16];
#pragma unroll
            for (int i = 0; i < 16; i++) {
                wA[i] = wp[(size_t)(half * 16 + i) * OF + oA];
                wB[i] = wp[(size_t)(half * 16 + i) * OF + oB];
            }
#pragma unroll
            for (int i = 0; i < 16; i++) {
                ull wvA = pk2(wA[i], wA[i]);
                ull wvB = pk2(wB[i], wB[i]);
                const float* cp = &cst[(dq * 32 + half * 16 + i) * KC];
                ull a0, a1, a2, a3, a4, a5, a6, a7;
                lds_v2u64(a0, a1, cp);
                lds_v2u64(a2, a3, cp + 8);
                lds_v2u64(a4, a5, cp + 4);
                lds_v2u64(a6, a7, cp + 12);
                accA[0] = fma2(a0, wvA, accA[0]);
                accA[1] = fma2(a1, wvA, accA[1]);
                accA[2] = fma2(a2, wvA, accA[2]);
                accA[3] = fma2(a3, wvA, accA[3]);
                accA[4] = fma2(a4, wvA, accA[4]);
                accA[5] = fma2(a5, wvA, accA[5]);
                accA[6] = fma2(a6, wvA, accA[6]);
                accA[7] = fma2(a7, wvA, accA[7]);
                accB[0] = fma2(a0, wvB, accB[0]);
                accB[1] = fma2(a1, wvB, accB[1]);
                accB[2] = fma2(a2, wvB, accB[2]);
                accB[3] = fma2(a3, wvB, accB[3]);
                accB[4] = fma2(a4, wvB, accB[4]);
                accB[5] = fma2(a5, wvB, accB[5]);
                accB[6] = fma2(a6, wvB, accB[6]);
                accB[7] = fma2(a7, wvB, accB[7]);
            }
        }

        const int kmap[8] = {0, 1, 4, 5, 2, 3, 6, 7};

        if (dq != 0) {
#pragma unroll
            for (int p = 0; p < 8; p++) {
                float v0, v1, u0, u1;
                upk2(accA[p], v0, v1);
                upk2(accB[p], u0, u1);
                int kp = kmap[p];
                red[(((dq - 1) * KC) + kp * 2 + 0) * 128 + col]      = v0;
                red[(((dq - 1) * KC) + kp * 2 + 1) * 128 + col]      = v1;
                red[(((dq - 1) * KC) + kp * 2 + 0) * 128 + col + 64] = u0;
                red[(((dq - 1) * KC) + kp * 2 + 1) * 128 + col + 64] = u1;
            }
        }
        __syncthreads();
        if (dq == 0) {
#pragma unroll
            for (int p = 0; p < 8; p++) {
                float v0, v1, u0, u1;
                upk2(accA[p], v0, v1);
                upk2(accB[p], u0, u1);
                int k0 = kmap[p] * 2, k1 = k0 + 1;
                v0 = v0 + red[(0 * KC + k0) * 128 + col]
                        + red[(1 * KC + k0) * 128 + col]
                        + red[(2 * KC + k0) * 128 + col];
                v1 = v1 + red[(0 * KC + k1) * 128 + col]
                        + red[(1 * KC + k1) * 128 + col]
                        + red[(2 * KC + k1) * 128 + col];
                u0 = u0 + red[(0 * KC + k0) * 128 + col + 64]
                        + red[(1 * KC + k0) * 128 + col + 64]
                        + red[(2 * KC + k0) * 128 + col + 64];
                u1 = u1 + red[(0 * KC + k1) * 128 + col + 64]
                        + red[(1 * KC + k1) * 128 + col + 64]
                        + red[(2 * KC + k1) * 128 + col + 64];
                g_lut[(size_t)(c * KC + k0) * OF + oA] = v0;
                g_lut[(size_t)(c * KC + k1) * OF + oA] = v1;
                g_lut[(size_t)(c * KC + k0) * OF + oB] = u0;
                g_lut[(size_t)(c * KC + k1) * OF + oB] = u1;
            }
        }
    }
}

// ---------------------------------------------------------------------------
// K3: gather v4 — R13 gather + MLP-batched staging (the R7/R8 fix applied
// here): 8 independent lut LDG.128 + 2 idx LDG.128 held in registers before
// any STS, instead of the dependent LDG->STS loop. Same data, same main loop
// -> same output bits.
// ---------------------------------------------------------------------------
__global__ __launch_bounds__(512, 2) void gather_kernel(float* __restrict__ out,
                                                        const float* __restrict__ bias)
{
    extern __shared__ float sm[];
    float*         lut_s = sm;                                  // [512][32] floats
    unsigned char* idx_s = (unsigned char*)(sm + NC * KC * 32); // 512*32 B

    const int ob  = blockIdx.x * 32;
    const int tb  = blockIdx.y * 512;
    const int tid = threadIdx.x;

    // batched staging: 4096 lut float4s (8/thread) + 1024 idx uint4s (2/thread)
    {
        float4 lbuf[8];
        uint4  ibuf[2];
#pragma unroll
        for (int j = 0; j < 8; j++) {
            int i   = tid + j * 512;
            int row = i >> 3;
            int col = (i & 7) * 4;
            lbuf[j] = *(const float4*)&g_lut[(size_t)row * OF + ob + col];
        }
        {
            const uint4* src = (const uint4*)&g_idx[(size_t)tb * NC];
            ibuf[0] = src[tid];
            ibuf[1] = src[tid + 512];
        }
#pragma unroll
        for (int j = 0; j < 8; j++) {
            int i   = tid + j * 512;
            int row = i >> 3;
            int col = (i & 7) * 4;
            *(float4*)&lut_s[row * 32 + col] = lbuf[j];
        }
        {
            uint4* dst = (uint4*)idx_s;
            dst[tid]       = ibuf[0];
            dst[tid + 512] = ibuf[1];
        }
    }
    __syncthreads();

    const int oq = tid & 7;
    const int tg = tid >> 3;
    const float4 bv = *(const float4*)&bias[ob + oq * 4];
    const float* lut_q = lut_s + oq * 4;

    for (int t = tg; t < 512; t += 64) {
        uint4 a = *(const uint4*)&idx_s[t * NC];
        uint4 b = *(const uint4*)&idx_s[t * NC + 16];
        unsigned int iw[8] = {a.x, a.y, a.z, a.w, b.x, b.y, b.z, b.w};
        float x0 = 0.f, y0 = 0.f, z0 = 0.f, w0 = 0.f;
        float x1 = 0.f, y1 = 0.f, z1 = 0.f, w1 = 0.f;
#pragma unroll
        for (int c = 0; c < NC; c++) {
            unsigned int k = (iw[c >> 2] >> ((c & 3) * 8)) & 0xFFu;
            float4 v = *(const float4*)&lut_q[c * 512 + k * 32];
            if (c & 1) { x1 += v.x; y1 += v.y; z1 += v.z; w1 += v.w; }
            else       { x0 += v.x; y0 += v.y; z0 += v.z; w0 += v.w; }
        }
        float4 r;
        r.x = (x0 + x1) + bv.x;
        r.y = (y0 + y1) + bv.y;
        r.z = (z0 + z1) + bv.z;
        r.w = (w0 + w1) + bv.w;
        *(float4*)&out[(size_t)(tb + t) * OF + ob + oq * 4] = r;
    }
}

// ---------------------------------------------------------------------------
extern "C" void kernel_launch(void* const* d_in, const int* in_sizes, int n_in,
                              void* d_out, int out_size)
{
    const float* x      = (const float*)d_in[0];
    const float* cent   = (const float*)d_in[1];
    const float* weight = (const float*)d_in[2];
    const float* bias   = (const float*)d_in[4];
    float* out = (float*)d_out;

    const int ntok = in_sizes[0] / INF;

    const int FUSED_SMEM = IDX_FLOATS * (int)sizeof(float);
    const int G_SMEM     = NC * KC * 32 * (int)sizeof(float) + 512 * NC;

    cudaFuncSetAttribute(fused_idx_lut, cudaFuncAttributeMaxDynamicSharedMemorySize, FUSED_SMEM);
    cudaFuncSetAttribute(gather_kernel, cudaFuncAttributeMaxDynamicSharedMemorySize, G_SMEM);

    const int nblk = (ntok / 128) * NC;      // 512
    fused_idx_lut<<<nblk * 2, 256, FUSED_SMEM>>>(x, cent, weight);
    gather_kernel<<<dim3(OF / 32, ntok / 512), 512, G_SMEM>>>(out, bias);
}